// round 3
// baseline (speedup 1.0000x reference)
#include <cuda_runtime.h>
#include <math.h>

typedef unsigned long long ull;

#define E_   128
#define N_   384

// ---------------- device scratch ----------------
__device__ float g_qkout[E_ * 768];     // q | k | v
__device__ float g_x[E_ * 256];         // after norm2
__device__ float g_pe[N_ * 384];        // positional encoding
__device__ float g_nq[N_ * 256];
__device__ float g_offatt[N_ * 384];    // off(256) | attw raw(128)
__device__ float g_ref[N_ * 2];
__device__ int   g_lx[N_ * 4];
__device__ int   g_ly[N_ * 4];
__device__ float g_agg[N_ * 2048];
__device__ float g_csum[N_ * 8];
__device__ float g_out256[N_ * 256];
__device__ float g_ca[N_ * 256];
__device__ float g_x2[E_ * 256];
__device__ float g_hid[E_ * 1024];
__device__ float g_ffn[2 * E_ * 256];   // split-K partials

// ---------------- f32x2 helpers ----------------
__device__ __forceinline__ ull pack2(float lo, float hi) {
    ull r;
    asm("mov.b64 %0, {%1, %2};" : "=l"(r)
        : "r"(__float_as_uint(lo)), "r"(__float_as_uint(hi)));
    return r;
}
__device__ __forceinline__ void fma2(ull& d, ull a, ull b) {
    asm("fma.rn.f32x2 %0, %1, %2, %0;" : "+l"(d) : "l"(a), "l"(b));
}
__device__ __forceinline__ float2 unpack2(ull v) {
    unsigned lo, hi;
    asm("mov.b64 {%0, %1}, %2;" : "=r"(lo), "=r"(hi) : "l"(v));
    return make_float2(__uint_as_float(lo), __uint_as_float(hi));
}

__device__ __forceinline__ float warp_sum(float v) {
#pragma unroll
    for (int o = 16; o; o >>= 1) v += __shfl_xor_sync(0xffffffffu, v, o);
    return v;
}
__device__ __forceinline__ float warp_max(float v) {
#pragma unroll
    for (int o = 16; o; o >>= 1) v = fmaxf(v, __shfl_xor_sync(0xffffffffu, v, o));
    return v;
}

__device__ __forceinline__ float block_ln256(float y, const float* w, const float* b, int t) {
    __shared__ float red[8];
    int lane = t & 31, wp = t >> 5;
    float s = warp_sum(y);
    if (lane == 0) red[wp] = s;
    __syncthreads();
    float tot = 0.f;
#pragma unroll
    for (int i = 0; i < 8; i++) tot += red[i];
    float mean = tot * (1.0f / 256.0f);
    __syncthreads();
    float dev = y - mean;
    float s2 = warp_sum(dev * dev);
    if (lane == 0) red[wp] = s2;
    __syncthreads();
    float tot2 = 0.f;
#pragma unroll
    for (int i = 0; i < 8; i++) tot2 += red[i];
    float var = tot2 * (1.0f / 256.0f);
    return dev * rsqrtf(var + 1e-5f) * w[t] + b[t];
}

// ================= geometry (device func, callable from fused launch) ========
__device__ void geom_body(const float* __restrict__ edge, int n) {
    int e = n / 3, p = n % 3;
    float ax = edge[e * 4 + 0], ay = edge[e * 4 + 1];
    float bx = edge[e * 4 + 2], by = edge[e * 4 + 3];
    float tpar = (float)p / 2.0f;
    float ptx = ax + tpar * (bx - ax);
    float pty = ay + tpar * (by - ay);
    float cxf = floorf(ptx), cyf = floorf(pty);
    int icx = (int)cxf, icy = (int)cyf;
    int minx = max(icx - 128, 0); if (minx + 256 > 2048) minx = 1792;
    int miny = max(icy - 128, 0); if (miny + 256 > 2048) miny = 1792;
    float fminx = (float)minx, fminy = (float)miny;
    float dx = bx - ax, dy = by - ay;

    float tlx, thx, tly, thy;
    {
        float safe = (dx == 0.f) ? 1.f : dx;
        float t1 = (fminx - ax) / safe, t2 = (fminx + 256.f - ax) / safe;
        tlx = (dx == 0.f) ? 0.f : fminf(t1, t2);
        thx = (dx == 0.f) ? 1.f : fmaxf(t1, t2);
    }
    {
        float safe = (dy == 0.f) ? 1.f : dy;
        float t1 = (fminy - ay) / safe, t2 = (fminy + 256.f - ay) / safe;
        tly = (dy == 0.f) ? 0.f : fminf(t1, t2);
        thy = (dy == 0.f) ? 1.f : fmaxf(t1, t2);
    }
    float t0 = fmaxf(fmaxf(tlx, tly), 0.f);
    float t1v = fmaxf(fminf(fminf(thx, thy), 1.f), t0);
    float cax = ax + t0 * dx, cay = ay + t0 * dy;
    float cbx = ax + t1v * dx, cby = ay + t1v * dy;

    float posx[3] = {cax, cbx, (float)icx};
    float posy[3] = {cay, cby, (float)icy};
    float* pe = g_pe + (size_t)n * 384;
    for (int k = 0; k < 32; k++) {
        float T = (float)pow(10000.0, (double)k / 32.0);
#pragma unroll
        for (int comp = 0; comp < 3; comp++) {
            float sy, cy2, sx, cx2;
            sincosf(posy[comp] / T, &sy, &cy2);
            sincosf(posx[comp] / T, &sx, &cx2);
            pe[comp * 128 + 2 * k]          = sy;
            pe[comp * 128 + 2 * k + 1]      = cy2;
            pe[comp * 128 + 64 + 2 * k]     = sx;
            pe[comp * 128 + 64 + 2 * k + 1] = cx2;
        }
    }
    g_ref[n * 2 + 0] = ((float)icx - fminx) / 256.f;
    g_ref[n * 2 + 1] = ((float)icy - fminy) / 256.f;
    const float ratio[4] = {8.f, 16.f, 32.f, 64.f};
#pragma unroll
    for (int l = 0; l < 4; l++) {
        g_lx[n * 4 + l] = (int)rintf(fminx / ratio[l]);
        g_ly[n * 4 + l] = (int)rintf(fminy / ratio[l]);
    }
}

// ================= GEMM: 16(M) x 64(O) tiles, f32x2 inner =================
// C[M,O] = A'[M,K] @ Wsel[O,K]^T + bias.
// grid: (x = O/64 [+geom flag uses y==My], y = M/16 (+1 if geom), z = ksplits)
// amode 0: A'=A ; amode 1: A'=A+A2 when o0<a2lim ; amode 2: concat [g_x+A2 | g_pe]
__global__ __launch_bounds__(256) void k_gemm3(
    const float* __restrict__ A, const float* __restrict__ A2,
    const float* __restrict__ W, const float* __restrict__ W2,
    const float* __restrict__ bias, const float* __restrict__ bias2,
    float* __restrict__ C, int M, int O, int K,
    int o_split, int a2lim, int amode, int relu,
    int kchunk, int geom_my, const float* __restrict__ edge)
{
    int t = threadIdx.x;
    if (geom_my >= 0 && (int)blockIdx.y == geom_my) {
        int n = blockIdx.x * 256 + t;
        if (blockIdx.x < 2 && n < N_) geom_body(edge, n);
        return;
    }
    __shared__ float As[2 * 16 * 34];
    __shared__ float Ws[2 * 32 * 72];
    int tx = t & 15;               // o-quad
    int mi = t >> 4;               // local m row (0..15)
    int m0 = blockIdx.y * 16, o0 = blockIdx.x * 64;
    int kstart = blockIdx.z * kchunk;

    // A tile load map: row ar (0..15), cols ac..ac+1
    int ar = t >> 4, ac = (t & 15) * 2;
    // W tile load map: o row wr (0..63), k cols wc..wc+7
    int wr = t & 63, wc = (t >> 6) * 8;

    bool addA2 = (amode == 1) && (o0 < a2lim);
    int orow = o0 + wr;
    const float* Wrow = (o_split > 0 && orow >= o_split)
                        ? (W2 + (size_t)(orow - o_split) * K)
                        : (W + (size_t)orow * K);

    ull acc01 = pack2(0.f, 0.f), acc23 = pack2(0.f, 0.f);

    int nk = kchunk >> 5;
    float2 pa;
    float4 pw0, pw1;

    auto fetch = [&](int kt) {
        int kgA = kstart + kt * 32 + ac;
        int m = m0 + ar;
        if (amode == 2) {
            if (kgA < 256) {
                int e = m / 3;
                float2 x = *(const float2*)(A + (size_t)e * 256 + kgA);
                float2 q = *(const float2*)(A2 + (size_t)e * 256 + kgA);
                pa = make_float2(x.x + q.x, x.y + q.y);
            } else {
                pa = *(const float2*)(g_pe + (size_t)m * 384 + (kgA - 256));
            }
        } else {
            float2 x = *(const float2*)(A + (size_t)m * K + kgA);
            if (addA2) {
                float2 q = *(const float2*)(A2 + (size_t)m * K + kgA);
                x = make_float2(x.x + q.x, x.y + q.y);
            }
            pa = x;
        }
        int kgW = kstart + kt * 32 + wc;
        pw0 = *(const float4*)(Wrow + kgW);
        pw1 = *(const float4*)(Wrow + kgW + 4);
    };
    auto store = [&](int s) {
        float* as = As + s * (16 * 34);
        float* ws = Ws + s * (32 * 72);
        *(float2*)(as + ar * 34 + ac) = pa;
        ws[(wc + 0) * 72 + wr] = pw0.x;
        ws[(wc + 1) * 72 + wr] = pw0.y;
        ws[(wc + 2) * 72 + wr] = pw0.z;
        ws[(wc + 3) * 72 + wr] = pw0.w;
        ws[(wc + 4) * 72 + wr] = pw1.x;
        ws[(wc + 5) * 72 + wr] = pw1.y;
        ws[(wc + 6) * 72 + wr] = pw1.z;
        ws[(wc + 7) * 72 + wr] = pw1.w;
    };

    fetch(0);
    store(0);
    __syncthreads();
    for (int kt = 0; kt < nk; kt++) {
        int s = kt & 1;
        if (kt + 1 < nk) fetch(kt + 1);
        const float* as = As + s * (16 * 34);
        const float* ws = Ws + s * (32 * 72);
#pragma unroll
        for (int kk = 0; kk < 32; kk++) {
            float a = as[mi * 34 + kk];
            ull ap = pack2(a, a);
            float4 w4 = *(const float4*)(ws + kk * 72 + tx * 4);
            fma2(acc01, ap, pack2(w4.x, w4.y));
            fma2(acc23, ap, pack2(w4.z, w4.w));
        }
        if (kt + 1 < nk) {
            __syncthreads();
            store(s ^ 1);
            __syncthreads();
        }
    }

    float2 p0 = unpack2(acc01);
    float2 p1 = unpack2(acc23);
    float vals[4] = {p0.x, p0.y, p1.x, p1.y};
    int m = m0 + mi;
    float4 outv;
    float* ov = (float*)&outv;
#pragma unroll
    for (int j = 0; j < 4; j++) {
        int o = o0 + tx * 4 + j;
        float b = 0.f;
        if (blockIdx.z == 0)
            b = (o_split > 0 && o >= o_split) ? bias2[o - o_split] : bias[o];
        float v = vals[j] + b;
        if (relu) v = fmaxf(v, 0.f);
        ov[j] = v;
    }
    *(float4*)(C + (size_t)blockIdx.z * M * O + (size_t)m * O + o0 + tx * 4) = outv;
}

// ================= self-attn + out-proj + residual + norm2 =================
__global__ __launch_bounds__(256) void k_attn(
    const float* __restrict__ wo, const float* __restrict__ bo,
    const float* __restrict__ tgt,
    const float* __restrict__ n2w, const float* __restrict__ n2b)
{
    int e = blockIdx.x, t = threadIdx.x;
    __shared__ float sq[256];
    __shared__ float sc[1024];
    __shared__ __align__(16) float so[256];
    sq[t] = g_qkout[e * 768 + t];
    __syncthreads();
    const float scale = 0.17677669529663687f;
#pragma unroll
    for (int i = 0; i < 4; i++) {
        int idx = t + 256 * i;
        int h = idx >> 7, f = idx & 127;
        const float* kr = g_qkout + f * 768 + 256 + h * 32;
        const float* qr = sq + h * 32;
        float s = 0.f;
#pragma unroll
        for (int d = 0; d < 32; d++) s += qr[d] * kr[d];
        sc[idx] = s * scale;
    }
    __syncthreads();
    {
        int wp = t >> 5, lane = t & 31;
        float vals[4];
        float m = -1e30f;
#pragma unroll
        for (int i = 0; i < 4; i++) { vals[i] = sc[wp * 128 + lane + 32 * i]; m = fmaxf(m, vals[i]); }
        m = warp_max(m);
        float sum = 0.f;
#pragma unroll
        for (int i = 0; i < 4; i++) { vals[i] = expf(vals[i] - m); sum += vals[i]; }
        sum = warp_sum(sum);
        float inv = 1.0f / sum;
#pragma unroll
        for (int i = 0; i < 4; i++) sc[wp * 128 + lane + 32 * i] = vals[i] * inv;
    }
    __syncthreads();
    {
        int h = t >> 5;
        float acc = 0.f;
        for (int f = 0; f < 128; f++) acc += sc[h * 128 + f] * g_qkout[f * 768 + 512 + t];
        so[t] = acc;
    }
    __syncthreads();
    float y = bo[t] + tgt[e * 256 + t];
    {
        ull acc2 = pack2(0.f, 0.f);
        const ull* wr2 = (const ull*)(wo + (size_t)t * 256);
        const ull* sp2 = (const ull*)so;
#pragma unroll 16
        for (int u = 0; u < 128; u++) fma2(acc2, wr2[u], sp2[u]);
        float2 r = unpack2(acc2);
        y += r.x + r.y;
    }
    g_x[e * 256 + t] = block_ln256(y, n2w, n2b, t);
}

// ================= sampling: 512 threads, warp = (head, dim-half) ============
__global__ __launch_bounds__(512) void k_sample(
    const float* __restrict__ src, const unsigned char* __restrict__ msk,
    const float* __restrict__ vr)
{
    int n = blockIdx.x, t = threadIdx.x;
    __shared__ float sloc[256];
    __shared__ float saw[128];
    __shared__ float mh[8], sh[8];
    if (t >= 256 && t < 384) saw[t - 256] = g_offatt[n * 384 + t];
    if (t < 256) {
        const float slen[4] = {32.f, 16.f, 8.f, 4.f};
        int l = (t >> 3) & 3, xy = t & 1;
        float off = g_offatt[n * 384 + t];
        sloc[t] = g_ref[n * 2 + xy] * vr[l * 2 + xy] + off / slen[l];
    }
    __syncthreads();
    if (t < 8) {
        float m = -1e30f;
        for (int i = 0; i < 16; i++) m = fmaxf(m, saw[t * 16 + i]);
        float s = 0.f;
        for (int i = 0; i < 16; i++) s += expf(saw[t * 16 + i] - m);
        mh[t] = m; sh[t] = s;
    }
    __syncthreads();
    if (t < 128) {
        int h = t >> 4;
        saw[t] = expf(saw[t] - mh[h]) / sh[h];
    }
    __syncthreads();

    int w = t >> 5;
    int h = w >> 1, half = w & 1, lane = t & 31;
    int doff = half * 32 + lane;       // float4 index within row (0..63)
    float4 a0 = make_float4(0.f, 0.f, 0.f, 0.f);
    float csum = 0.f;
    const int s_arr[4]  = {32, 16, 8, 4};
    const int w_arr[4]  = {256, 128, 64, 32};
    const int st_arr[4] = {0, 65536, 81920, 86016};
#pragma unroll
    for (int l = 0; l < 4; l++) {
        int s = s_arr[l], W = w_arr[l], base = st_arr[l];
        int lxl = g_lx[n * 4 + l], lyl = g_ly[n * 4 + l];
#pragma unroll
        for (int p = 0; p < 4; p++) {
            float gx = sloc[h * 32 + l * 8 + p * 2 + 0];
            float gy = sloc[h * 32 + l * 8 + p * 2 + 1];
            float a  = saw[h * 16 + l * 4 + p];
            float px = gx * (float)s - 0.5f;
            float py = gy * (float)s - 0.5f;
            float fx0 = floorf(px), fy0 = floorf(py);
            int x0 = (int)fx0, y0 = (int)fy0;
            float fx = px - fx0, fy = py - fy0;
            float wts[4] = {(1.f - fx) * (1.f - fy), fx * (1.f - fy),
                            (1.f - fx) * fy, fx * fy};
            int xs[4] = {x0, x0 + 1, x0, x0 + 1};
            int ys[4] = {y0, y0, y0 + 1, y0 + 1};
#pragma unroll
            for (int tp = 0; tp < 4; tp++) {
                int xi = xs[tp], yi = ys[tp];
                bool ok = (xi >= 0) & (xi < s) & (yi >= 0) & (yi < s);
                int xc = min(max(xi, 0), s - 1);
                int yc = min(max(yi, 0), s - 1);
                int pix = base + (lyl + yc) * W + (lxl + xc);
                ok = ok && !msk[pix];
                float c = ok ? a * wts[tp] : 0.f;
                csum += c;
                float4 v0 = __ldg((const float4*)(src + (size_t)pix * 256) + doff);
                a0.x += c * v0.x; a0.y += c * v0.y; a0.z += c * v0.z; a0.w += c * v0.w;
            }
        }
    }
    ((float4*)(g_agg + (size_t)n * 2048 + h * 256))[doff] = a0;
    if (half == 0 && lane == 0) g_csum[n * 8 + h] = csum;
}

// ================= per-head value projection =================
__global__ __launch_bounds__(256) void k_headgemm(
    const float* __restrict__ valw, const float* __restrict__ valb)
{
    __shared__ float sw[32 * 258];
    int t = threadIdx.x;
    int h = blockIdx.y;
    int n0 = blockIdx.x * 64;
    for (int i = 0; i < 32; i++) {
        int idx = t + 256 * i;
        int r = idx >> 8, c = idx & 255;
        sw[r * 258 + c] = valw[(size_t)(h * 32 + r) * 256 + c];
    }
    __syncthreads();
    int j = t & 31, nb = t >> 5;
    float vb = valb[h * 32 + j];
#pragma unroll
    for (int i = 0; i < 8; i++) {
        int n = n0 + nb + 8 * i;
        const ull* ar2 = (const ull*)(g_agg + (size_t)n * 2048 + h * 256);
        ull acc2 = pack2(0.f, 0.f);
#pragma unroll 8
        for (int d2 = 0; d2 < 128; d2++) {
            ull w2 = *(const ull*)(sw + j * 258 + d2 * 2);
            fma2(acc2, __ldg(ar2 + d2), w2);
        }
        float2 r = unpack2(acc2);
        g_out256[(size_t)n * 256 + h * 32 + j] = r.x + r.y + g_csum[n * 8 + h] * vb;
    }
}

// ================= pooled mean + residual + norm1 =================
__global__ __launch_bounds__(256) void k_pool_ln(
    const float* __restrict__ n1w, const float* __restrict__ n1b)
{
    int e = blockIdx.x, t = threadIdx.x;
    float pooled = (g_ca[(3 * e + 0) * 256 + t] + g_ca[(3 * e + 1) * 256 + t] +
                    g_ca[(3 * e + 2) * 256 + t]) / 3.0f;
    float y = g_x[e * 256 + t] + pooled;
    g_x2[e * 256 + t] = block_ln256(y, n1w, n1b, t);
}

// ================= final: sum split-K partials + residual + norm3 ============
__global__ __launch_bounds__(256) void k_final_ln(
    const float* __restrict__ n3w, const float* __restrict__ n3b,
    float* __restrict__ out)
{
    int e = blockIdx.x, t = threadIdx.x;
    float y = g_x2[e * 256 + t] + g_ffn[e * 256 + t] + g_ffn[E_ * 256 + e * 256 + t];
    out[e * 256 + t] = block_ln256(y, n3w, n3b, t);
}

// ================= launch =================
extern "C" void kernel_launch(void* const* d_in, const int* in_sizes, int n_in,
                              void* d_out, int out_size) {
    const float* tgt      = (const float*)d_in[0];
    const float* qpos     = (const float*)d_in[1];
    const float* edge     = (const float*)d_in[2];
    const float* src      = (const float*)d_in[3];
    const unsigned char* msk = (const unsigned char*)d_in[4];
    const float* vr       = (const float*)d_in[5];
    const float* inw      = (const float*)d_in[6];
    const float* inb      = (const float*)d_in[7];
    const float* ow       = (const float*)d_in[8];
    const float* ob       = (const float*)d_in[9];
    const float* n1w      = (const float*)d_in[10];
    const float* n1b      = (const float*)d_in[11];
    const float* n2w      = (const float*)d_in[12];
    const float* n2b      = (const float*)d_in[13];
    const float* n3w      = (const float*)d_in[14];
    const float* n3b      = (const float*)d_in[15];
    const float* l0w      = (const float*)d_in[16];
    const float* l0b      = (const float*)d_in[17];
    const float* l1w      = (const float*)d_in[18];
    const float* l1b      = (const float*)d_in[19];
    const float* l2w      = (const float*)d_in[20];
    const float* l2b      = (const float*)d_in[21];
    const float* offw     = (const float*)d_in[22];
    const float* offb     = (const float*)d_in[23];
    const float* attww    = (const float*)d_in[24];
    const float* attwb    = (const float*)d_in[25];
    const float* valw     = (const float*)d_in[26];
    const float* valb     = (const float*)d_in[27];
    const float* oprojw   = (const float*)d_in[28];
    const float* oprojb   = (const float*)d_in[29];
    float* out = (float*)d_out;

    float *gqkout, *gx, *gnq, *goffatt, *gout256, *gca, *gx2, *ghid, *gffn;
    cudaGetSymbolAddress((void**)&gqkout, g_qkout);
    cudaGetSymbolAddress((void**)&gx, g_x);
    cudaGetSymbolAddress((void**)&gnq, g_nq);
    cudaGetSymbolAddress((void**)&goffatt, g_offatt);
    cudaGetSymbolAddress((void**)&gout256, g_out256);
    cudaGetSymbolAddress((void**)&gca, g_ca);
    cudaGetSymbolAddress((void**)&gx2, g_x2);
    cudaGetSymbolAddress((void**)&ghid, g_hid);
    cudaGetSymbolAddress((void**)&gffn, g_ffn);

    // fused: QKV projection (96 gemm blocks) + geometry (row y==8)
    k_gemm3<<<dim3(12, 9), 256>>>(tgt, qpos, inw, nullptr, inb, nullptr,
                                  gqkout, 128, 768, 256, 0, 512, 1, 0,
                                  256, 8, edge);
    // self-attn + out-proj + norm2
    k_attn<<<128, 256>>>(ow, ob, tgt, n2w, n2b);
    // lin0 on [x+qpos | pe]
    k_gemm3<<<dim3(4, 24), 256>>>(gx, qpos, l0w, nullptr, l0b, nullptr,
                                  gnq, 384, 256, 640, 0, 0, 2, 0,
                                  640, -1, nullptr);
    // fused offsets + attention-weight logits
    k_gemm3<<<dim3(6, 24), 256>>>(gnq, nullptr, offw, attww, offb, attwb,
                                  goffatt, 384, 384, 256, 256, 0, 0, 0,
                                  256, -1, nullptr);
    // deformable sampling
    k_sample<<<384, 512>>>(src, msk, vr);
    // per-head value projection
    k_headgemm<<<dim3(6, 8), 256>>>(valw, valb);
    // output projection
    k_gemm3<<<dim3(4, 24), 256>>>(gout256, nullptr, oprojw, nullptr, oprojb, nullptr,
                                  gca, 384, 256, 256, 0, 0, 0, 0,
                                  256, -1, nullptr);
    // pool + norm1
    k_pool_ln<<<128, 256>>>(n1w, n1b);
    // FFN
    k_gemm3<<<dim3(16, 8), 256>>>(gx2, nullptr, l1w, nullptr, l1b, nullptr,
                                  ghid, 128, 1024, 256, 0, 0, 0, 1,
                                  256, -1, nullptr);
    k_gemm3<<<dim3(4, 8, 2), 256>>>(ghid, nullptr, l2w, nullptr, l2b, nullptr,
                                    gffn, 128, 256, 1024, 0, 0, 0, 0,
                                    512, -1, nullptr);
    // final norm (sums split-K partials)
    k_final_ln<<<128, 256>>>(n3w, n3b, out);
}